// round 1
// baseline (speedup 1.0000x reference)
#include <cuda_runtime.h>
#include <cuda_bf16.h>

#define NFEAT 17
#define NEV 16
#define PPE 65536
#define NPTS (NEV * PPE)
#define MAXCOND 2048
#define T_B 0.2f
#define R2 0.49f

// Scratch (device globals — no allocation allowed)
__device__ float4 g_pts[NPTS];      // (c0, c1, c2, beta) packed
__device__ float  g_beta[NPTS];     // contiguous betas for fast argmax scans
__device__ int    g_cidx[NEV * MAXCOND];
__device__ int    g_ccnt[NEV];

// ---------------------------------------------------------------------------
// 1) Zero-fill the whole output (output is mostly zeros; d_out is poisoned).
// ---------------------------------------------------------------------------
__global__ void zero_kernel(float* __restrict__ out, long long n) {
    long long i  = (long long)blockIdx.x * blockDim.x + threadIdx.x;
    long long i4 = i * 4;
    if (i4 + 3 < n) {
        float4 z; z.x = 0.f; z.y = 0.f; z.z = 0.f; z.w = 0.f;
        reinterpret_cast<float4*>(out)[i] = z;
    } else if (i4 < n) {
        for (long long j = i4; j < n; ++j) out[j] = 0.f;
    }
}

// ---------------------------------------------------------------------------
// 2) Pack betas + ccoords out of the 17-wide x rows.
//    beta = x[:,9], ccoords = x[:,14:17]
// ---------------------------------------------------------------------------
__global__ void pack_kernel(const float* __restrict__ x) {
    int i = blockIdx.x * blockDim.x + threadIdx.x;
    if (i >= NPTS) return;
    const float* r = x + (long long)i * NFEAT;
    float4 p;
    p.x = r[14];
    p.y = r[15];
    p.z = r[16];
    p.w = r[9];
    g_pts[i]  = p;
    g_beta[i] = p.w;
}

// ---------------------------------------------------------------------------
// 3) Greedy condensation. One block per event, 1024 threads.
//    Each thread owns 64 points (stride-1024 interleave); assignment state is
//    a 64-bit register mask. Loop until max unassigned beta < 0.2.
// ---------------------------------------------------------------------------
__global__ void __launch_bounds__(1024, 1) condense_kernel() {
    const int e = blockIdx.x;
    const int t = threadIdx.x;
    const float4* __restrict__ pts  = g_pts  + e * PPE;
    const float*  __restrict__ beta = g_beta + e * PPE;

    __shared__ float  sb[1024];
    __shared__ int    si[1024];
    __shared__ float4 sref;

    unsigned long long assigned = 0ULL;
    int count = 0;

    for (int iter = 0; iter < MAXCOND; ++iter) {
        // ---- Phase A: per-thread argmax over unassigned points ----
        float best = -1.0f;
        int   bidx = 0x7FFFFFFF;
        #pragma unroll 8
        for (int k = 0; k < 64; ++k) {
            if ((assigned >> k) & 1ULL) continue;
            int i  = t + (k << 10);
            float b = beta[i];
            // within a thread, i is ascending, so strict '>' keeps the first max
            if (b > best) { best = b; bidx = i; }
        }
        sb[t] = best; si[t] = bidx;
        __syncthreads();

        // tree reduction with first-index tie-break (matches jnp.argmax)
        for (int s = 512; s > 0; s >>= 1) {
            if (t < s) {
                float b2 = sb[t + s]; int i2 = si[t + s];
                if (b2 > sb[t] || (b2 == sb[t] && i2 < si[t])) {
                    sb[t] = b2; si[t] = i2;
                }
            }
            __syncthreads();
        }

        float maxb = sb[0];
        int   ref  = si[0];
        if (!(maxb >= T_B)) break;

        if (t == 0) {
            sref = pts[ref];
            g_cidx[e * MAXCOND + count] = ref;
        }
        __syncthreads();

        // ---- Phase B: assign unassigned points within radius ----
        float cx = sref.x, cy = sref.y, cz = sref.z;
        #pragma unroll 8
        for (int k = 0; k < 64; ++k) {
            if ((assigned >> k) & 1ULL) continue;
            int i = t + (k << 10);
            float4 p = pts[i];
            float dx = p.x - cx;
            float dy = p.y - cy;
            float dz = p.z - cz;
            float d2 = dx * dx + dy * dy + dz * dz;
            if (d2 <= R2) assigned |= (1ULL << k);
        }
        ++count;
        // next iteration's sb/si writes are fenced by the reduction barriers
    }

    if (t == 0) g_ccnt[e] = count;
}

// ---------------------------------------------------------------------------
// 4) Scatter condensate rows: out[row,:] = x[row,:]. One block per event.
// ---------------------------------------------------------------------------
__global__ void scatter_kernel(const float* __restrict__ x, float* __restrict__ out) {
    int e    = blockIdx.x;
    int cnt  = g_ccnt[e];
    int warp = threadIdx.x >> 5;
    int lane = threadIdx.x & 31;
    int nw   = blockDim.x >> 5;
    for (int c = warp; c < cnt; c += nw) {
        long long row = (long long)e * PPE + g_cidx[e * MAXCOND + c];
        if (lane < NFEAT)
            out[row * NFEAT + lane] = x[row * NFEAT + lane];
    }
}

// ---------------------------------------------------------------------------
// 5) Row splits: cumulative condensate counts, appended as float32.
// ---------------------------------------------------------------------------
__global__ void splits_kernel(float* __restrict__ out, long long off) {
    if (blockIdx.x == 0 && threadIdx.x == 0) {
        int acc = 0;
        out[off] = 0.0f;
        for (int e = 0; e < NEV; ++e) {
            acc += g_ccnt[e];
            out[off + 1 + e] = (float)acc;
        }
    }
}

// ---------------------------------------------------------------------------
extern "C" void kernel_launch(void* const* d_in, const int* in_sizes, int n_in,
                              void* d_out, int out_size) {
    const float* x   = (const float*)d_in[0];
    float*       out = (float*)d_out;
    long long    n   = (long long)out_size;

    // 1) zero-fill entire output
    long long n4 = (n + 3) / 4;
    int zb = (int)((n4 + 255) / 256);
    zero_kernel<<<zb, 256>>>(out, n);

    // 2) pack betas + coords
    pack_kernel<<<NPTS / 256, 256>>>(x);

    // 3) condensation (one block per event)
    condense_kernel<<<NEV, 1024>>>();

    // 4) scatter condensate rows
    scatter_kernel<<<NEV, 512>>>(x, out);

    // 5) row splits appended after the dout block (guard on expected layout)
    long long dout_elems = (long long)NPTS * NFEAT;
    if (n == dout_elems + NEV + 1) {
        splits_kernel<<<1, 32>>>(out, dout_elems);
    }
}

// round 2
// speedup vs baseline: 1.5903x; 1.5903x over previous
#include <cuda_runtime.h>
#include <cuda_bf16.h>

#define NFEAT 17
#define NEV 16
#define PPE 65536
#define NPTS (NEV * PPE)
#define MAXCOND 4096
#define T_B 0.2f
#define R2 0.49f

// Scratch (device globals — no allocation allowed)
__device__ float4 g_pts[NPTS];      // (c0, c1, c2, beta) packed
__device__ float  g_beta[NPTS];     // contiguous betas for the initial argmax
__device__ int    g_cidx[NEV * MAXCOND];
__device__ int    g_ccnt[NEV];

// ---------------------------------------------------------------------------
// 1) Fused zero-fill + pack.
//    Zero the whole output (grid-stride float4), and extract (c14,c15,c16,beta=c9)
//    per point into g_pts / g_beta.
// ---------------------------------------------------------------------------
__global__ void zero_pack_kernel(const float* __restrict__ x,
                                 float* __restrict__ out, long long n) {
    const long long gid    = (long long)blockIdx.x * blockDim.x + threadIdx.x;
    const long long stride = (long long)gridDim.x * blockDim.x;

    // zero output (vectorized, grid-stride)
    const long long n4 = n >> 2;
    float4 z; z.x = 0.f; z.y = 0.f; z.z = 0.f; z.w = 0.f;
    for (long long j = gid; j < n4; j += stride)
        reinterpret_cast<float4*>(out)[j] = z;
    if (gid < (n & 3)) out[(n4 << 2) + gid] = 0.f;

    // pack (one point per thread; grid sized so gid covers NPTS exactly once)
    if (gid < NPTS) {
        const float* r = x + gid * NFEAT;
        float4 p;
        p.x = r[14];
        p.y = r[15];
        p.z = r[16];
        p.w = r[9];
        g_pts[gid]  = p;
        g_beta[gid] = p.w;
    }
}

// ---------------------------------------------------------------------------
// (b, i) argmax reduction across 1024 threads: warp shuffle + 32-entry smem.
// Tie-break: smallest index (matches jnp.argmax).
// ---------------------------------------------------------------------------
__device__ __forceinline__ void block_argmax(float& b, int& i,
                                             float* swb, int* swi, int t) {
    // warp-level
    #pragma unroll
    for (int off = 16; off > 0; off >>= 1) {
        float ob = __shfl_down_sync(0xFFFFFFFFu, b, off);
        int   oi = __shfl_down_sync(0xFFFFFFFFu, i, off);
        if (ob > b || (ob == b && oi < i)) { b = ob; i = oi; }
    }
    const int warp = t >> 5, lane = t & 31;
    if (lane == 0) { swb[warp] = b; swi[warp] = i; }
    __syncthreads();
    if (warp == 0) {
        b = swb[lane]; i = swi[lane];
        #pragma unroll
        for (int off = 16; off > 0; off >>= 1) {
            float ob = __shfl_down_sync(0xFFFFFFFFu, b, off);
            int   oi = __shfl_down_sync(0xFFFFFFFFu, i, off);
            if (ob > b || (ob == b && oi < i)) { b = ob; i = oi; }
        }
        if (lane == 0) { swb[0] = b; swi[0] = i; }
    }
    __syncthreads();
    b = swb[0]; i = swi[0];
}

// ---------------------------------------------------------------------------
// 2) Greedy condensation. One block per event, 1024 threads.
//    Per-thread 64-bit mask of UNASSIGNED points (stride-1024 interleave).
//    Each iteration: single ffs-walk over remaining bits computes distance to
//    the current ref, clears absorbed bits, and tracks the next argmax.
// ---------------------------------------------------------------------------
__global__ void __launch_bounds__(1024, 1) condense_kernel() {
    const int e = blockIdx.x;
    const int t = threadIdx.x;
    const float4* __restrict__ pts  = g_pts  + e * PPE;
    const float*  __restrict__ beta = g_beta + e * PPE;

    __shared__ float swb[32];
    __shared__ int   swi[32];

    unsigned long long rem = ~0ULL;   // unassigned mask (bit k -> point t + k*1024)
    int count = 0;

    // ---- initial argmax over all points (coalesced beta scan) ----
    float best = -1.0f;
    int   bidx = 0x7FFFFFFF;
    #pragma unroll
    for (int k = 0; k < 64; ++k) {
        float b = beta[t + (k << 10)];
        if (b > best) { best = b; bidx = t + (k << 10); }   // ascending i: '>' keeps first
    }
    block_argmax(best, bidx, swb, swi, t);

    while (best >= T_B) {
        const int ref = bidx;
        if (t == 0) g_cidx[e * MAXCOND + count] = ref;
        ++count;

        // broadcast ref coords (L2 broadcast load; all threads same address)
        const float4 rc = __ldg(&pts[ref]);
        const float cx = rc.x, cy = rc.y, cz = rc.z;

        // fused pass: clear absorbed bits, track next max over survivors
        best = -1.0f;
        bidx = 0x7FFFFFFF;
        unsigned long long m = rem;
        while (m) {
            const int k = __ffsll((long long)m) - 1;
            m &= m - 1;
            const int i = t + (k << 10);
            const float4 p = pts[i];
            const float dx = p.x - cx;
            const float dy = p.y - cy;
            const float dz = p.z - cz;
            const float d2 = dx * dx + dy * dy + dz * dz;
            if (d2 <= R2) {
                rem &= ~(1ULL << k);
            } else if (p.w > best) {                          // ascending i within thread
                best = p.w; bidx = i;
            }
        }
        block_argmax(best, bidx, swb, swi, t);
    }

    if (t == 0) g_ccnt[e] = count;
}

// ---------------------------------------------------------------------------
// 3) Scatter condensate rows: out[row,:] = x[row,:]. One block per event.
// ---------------------------------------------------------------------------
__global__ void scatter_kernel(const float* __restrict__ x, float* __restrict__ out) {
    const int e    = blockIdx.x;
    const int cnt  = g_ccnt[e];
    const int warp = threadIdx.x >> 5;
    const int lane = threadIdx.x & 31;
    const int nw   = blockDim.x >> 5;
    for (int c = warp; c < cnt; c += nw) {
        const long long row = (long long)e * PPE + g_cidx[e * MAXCOND + c];
        if (lane < NFEAT)
            out[row * NFEAT + lane] = x[row * NFEAT + lane];
    }
}

// ---------------------------------------------------------------------------
// 4) Row splits: cumulative condensate counts appended as float32.
// ---------------------------------------------------------------------------
__global__ void splits_kernel(float* __restrict__ out, long long off) {
    if (threadIdx.x == 0) {
        int acc = 0;
        out[off] = 0.0f;
        for (int e = 0; e < NEV; ++e) {
            acc += g_ccnt[e];
            out[off + 1 + e] = (float)acc;
        }
    }
}

// ---------------------------------------------------------------------------
extern "C" void kernel_launch(void* const* d_in, const int* in_sizes, int n_in,
                              void* d_out, int out_size) {
    const float* x   = (const float*)d_in[0];
    float*       out = (float*)d_out;
    const long long n = (long long)out_size;

    // 1) fused zero + pack: grid must cover NPTS one-thread-per-point
    zero_pack_kernel<<<NPTS / 256, 256>>>(x, out, n);

    // 2) condensation (one block per event)
    condense_kernel<<<NEV, 1024>>>();

    // 3) scatter condensate rows
    scatter_kernel<<<NEV, 512>>>(x, out);

    // 4) row splits appended after the dout block (guard on expected layout)
    const long long dout_elems = (long long)NPTS * NFEAT;
    if (n == dout_elems + NEV + 1) {
        splits_kernel<<<1, 32>>>(out, dout_elems);
    }
}